// round 10
// baseline (speedup 1.0000x reference)
#include <cuda_runtime.h>
#include <cuda_fp16.h>
#include <cstdint>

#define NN    100000
#define INCH  500
#define HID   64
#define OUTC  40
#define EMAX  3200000
#define NB    ((NN + 255) / 256)   // scan blocks = 391

// ---------------- scratch (device globals; zero-initialized at load) ----------------
__device__ float   g_dinv[NN];
__device__ int     g_cnt[NN];       // always zero between calls (scan_block re-zeroes)
__device__ int     g_off[NN];       // per-block exclusive scan (bscan folded lazily)
__device__ int     g_cur[NN];       // always zero between calls
__device__ int     g_bsum[512];
__device__ int     g_bscan[512];
__device__ int2    g_epk[EMAX];                 // (src, bitcast(weight)) grouped by dst
__device__ __half2 g_XWh[(size_t)NN * 32];      // x @ W_cons, fp16 pairs
__device__ __half2 g_Gh[(size_t)NN * 20];       // relu(agg1+b) @ W_cls, fp16 pairs

__device__ __forceinline__ int csr_off(int i, int E) {
    return (i >= NN) ? E : (g_off[i] + g_bscan[i >> 8]);
}

// ---------------- degree count ----------------
__global__ void k_count(const int* __restrict__ dst, int E) {
    int e = blockIdx.x * blockDim.x + threadIdx.x;
    if (e < E) atomicAdd(&g_cnt[dst[e]], 1);
}

// ---------------- per-block exclusive scan (dinv + re-zero fused) ----------------
__global__ void k_scan_block() {
    __shared__ int sh[256];
    int b = blockIdx.x, t = threadIdx.x;
    int i = b * 256 + t;
    int v = (i < NN) ? g_cnt[i] : 0;
    if (i < NN) {
        g_dinv[i] = rsqrtf((float)(v + 1));
        g_cnt[i] = 0;
        g_cur[i] = 0;
    }
    int x = v;
    sh[t] = x; __syncthreads();
#pragma unroll
    for (int d = 1; d < 256; d <<= 1) {
        int y = (t >= d) ? sh[t - d] : 0;
        __syncthreads();
        x += y; sh[t] = x;
        __syncthreads();
    }
    if (i < NN) g_off[i] = x - v;
    if (t == 255) g_bsum[b] = x;
}
__global__ void k_scan_tops() {
    __shared__ int sh[512];
    int t = threadIdx.x;
    int v = (t < NB) ? g_bsum[t] : 0;
    int x = v;
    sh[t] = x; __syncthreads();
#pragma unroll
    for (int d = 1; d < 512; d <<= 1) {
        int y = (t >= d) ? sh[t - d] : 0;
        __syncthreads();
        x += y; sh[t] = x;
        __syncthreads();
    }
    if (t < NB) g_bscan[t] = x - v;
}

// ---------------- CSR fill ----------------
__global__ void k_fill(const int* __restrict__ src, const int* __restrict__ dst, int E) {
    int e = blockIdx.x * blockDim.x + threadIdx.x;
    if (e >= E) return;
    int s = src[e];
    int d = dst[e];
    int pos = g_off[d] + g_bscan[d >> 8] + atomicAdd(&g_cur[d], 1);
    g_epk[pos] = make_int2(s, __float_as_int(g_dinv[s] * g_dinv[d]));
}

// ---------------- GEMM1 (tf32 tensor cores, reg-prefetch pipeline): XWh = x @ W_cons ----------------
__device__ __forceinline__ uint32_t f2tf32(float f) {
    uint32_t r;
    asm("cvt.rna.tf32.f32 %0, %1;" : "=r"(r) : "f"(f));
    return r;
}
__device__ __forceinline__ void mma_tf32(float* d, const uint32_t* a, const uint32_t* b) {
    asm volatile(
        "mma.sync.aligned.m16n8k8.row.col.f32.tf32.tf32.f32 "
        "{%0,%1,%2,%3}, {%4,%5,%6,%7}, {%8,%9}, {%0,%1,%2,%3};"
        : "+f"(d[0]), "+f"(d[1]), "+f"(d[2]), "+f"(d[3])
        : "r"(a[0]), "r"(a[1]), "r"(a[2]), "r"(a[3]), "r"(b[0]), "r"(b[1]));
}

__device__ __forceinline__ void g1_load(const float* __restrict__ X,
                                        const float* __restrict__ W,
                                        int row0, int k0, int tid,
                                        float4 aR[4], float4 bR[2]) {
    const int kq = (INCH - k0 >= 32) ? 8 : (INCH - k0) / 4;
#pragma unroll
    for (int n = 0; n < 4; n++) {
        int i = tid + n * 256;
        int r = i >> 3, q = i & 7;
        int gr = row0 + r;
        aR[n] = (gr < NN && q < kq)
            ? *reinterpret_cast<const float4*>(X + (size_t)gr * INCH + k0 + q * 4)
            : make_float4(0.f, 0.f, 0.f, 0.f);
    }
#pragma unroll
    for (int n = 0; n < 2; n++) {
        int i = tid + n * 256;
        int kk = i >> 4, q = i & 15;
        bR[n] = (k0 + kk < INCH)
            ? *reinterpret_cast<const float4*>(W + (size_t)(k0 + kk) * HID + q * 4)
            : make_float4(0.f, 0.f, 0.f, 0.f);
    }
}

__global__ void __launch_bounds__(256) k_gemm1(const float* __restrict__ X,
                                               const float* __restrict__ W) {
    __shared__ uint32_t As[32][132];
    __shared__ uint32_t Bs[32][68];

    const int row0 = blockIdx.x * 128;
    const int tid  = threadIdx.x;
    const int lane = tid & 31;
    const int wid  = tid >> 5;
    const int wm   = wid & 3;
    const int wn   = wid >> 2;
    const int g    = lane >> 2;
    const int q4   = lane & 3;

    float acc[2][4][4];
#pragma unroll
    for (int tm = 0; tm < 2; tm++)
#pragma unroll
        for (int tn = 0; tn < 4; tn++)
#pragma unroll
            for (int j = 0; j < 4; j++) acc[tm][tn][j] = 0.0f;

    float4 aR[4];
    float4 bR[2];
    g1_load(X, W, row0, 0, tid, aR, bR);

    const int NT = (INCH + 31) / 32;
    for (int kt = 0; kt < NT; kt++) {
#pragma unroll
        for (int n = 0; n < 4; n++) {
            int i = tid + n * 256;
            int r = i >> 3, q = i & 7;
            As[q * 4 + 0][r] = f2tf32(aR[n].x);
            As[q * 4 + 1][r] = f2tf32(aR[n].y);
            As[q * 4 + 2][r] = f2tf32(aR[n].z);
            As[q * 4 + 3][r] = f2tf32(aR[n].w);
        }
#pragma unroll
        for (int n = 0; n < 2; n++) {
            int i = tid + n * 256;
            int kk = i >> 4, q = i & 15;
            Bs[kk][q * 4 + 0] = f2tf32(bR[n].x);
            Bs[kk][q * 4 + 1] = f2tf32(bR[n].y);
            Bs[kk][q * 4 + 2] = f2tf32(bR[n].z);
            Bs[kk][q * 4 + 3] = f2tf32(bR[n].w);
        }
        __syncthreads();

        if (kt + 1 < NT) g1_load(X, W, row0, (kt + 1) * 32, tid, aR, bR);

#pragma unroll
        for (int ks = 0; ks < 4; ks++) {
            const int kk = ks * 8 + q4;
            uint32_t a[2][4];
#pragma unroll
            for (int tm = 0; tm < 2; tm++) {
                int r = wm * 32 + tm * 16 + g;
                a[tm][0] = As[kk][r];
                a[tm][1] = As[kk][r + 8];
                a[tm][2] = As[kk + 4][r];
                a[tm][3] = As[kk + 4][r + 8];
            }
            uint32_t b[4][2];
#pragma unroll
            for (int tn = 0; tn < 4; tn++) {
                int c = wn * 32 + tn * 8 + g;
                b[tn][0] = Bs[kk][c];
                b[tn][1] = Bs[kk + 4][c];
            }
#pragma unroll
            for (int tm = 0; tm < 2; tm++)
#pragma unroll
                for (int tn = 0; tn < 4; tn++)
                    mma_tf32(acc[tm][tn], a[tm], b[tn]);
        }
        __syncthreads();
    }

#pragma unroll
    for (int tm = 0; tm < 2; tm++) {
#pragma unroll
        for (int tn = 0; tn < 4; tn++) {
            int c2 = (wn * 32 + tn * 8 + q4 * 2) >> 1;
            int r = row0 + wm * 32 + tm * 16 + g;
            if (r < NN)
                g_XWh[(size_t)r * 32 + c2] = __floats2half2_rn(acc[tm][tn][0], acc[tm][tn][1]);
            if (r + 8 < NN)
                g_XWh[(size_t)(r + 8) * 32 + c2] = __floats2half2_rn(acc[tm][tn][2], acc[tm][tn][3]);
        }
    }
}

// ---------------- fused agg1 + gemm2: warp/node gather, then h @ W_cls ----------------
// grid = 12500 blocks x 256 thr (exactly NN warps)
__global__ void __launch_bounds__(256) k_agg1(const float* __restrict__ bcons,
                                              const float* __restrict__ Wcls, int E) {
    __shared__ float sWc[64 * 42];     // W_cls padded rows
    __shared__ float shh[8][64];       // per-warp h staging

    const int tid  = threadIdx.x;
    const int w    = tid >> 5;
    const int lane = tid & 31;
    const int node = blockIdx.x * 8 + w;

    for (int i = tid; i < 64 * 40; i += 256) {
        int k = i / 40, c = i - k * 40;
        sWc[k * 42 + c] = Wcls[i];
    }
    __syncthreads();

    const int beg = csr_off(node, E);
    const int end = csr_off(node + 1, E);

    float dd = g_dinv[node]; dd *= dd;
    float2 v0 = __half22float2(g_XWh[(size_t)node * 32 + lane]);
    float ax = dd * v0.x, ay = dd * v0.y;

    int i = beg;
    for (; i + 8 <= end; i += 8) {
        int2 ee[8];
#pragma unroll
        for (int u = 0; u < 8; u++) ee[u] = g_epk[i + u];
        float2 pp[8];
#pragma unroll
        for (int u = 0; u < 8; u++) pp[u] = __half22float2(g_XWh[(size_t)ee[u].x * 32 + lane]);
#pragma unroll
        for (int u = 0; u < 8; u++) {
            float wt = __int_as_float(ee[u].y);
            ax += wt * pp[u].x;
            ay += wt * pp[u].y;
        }
    }
    {   // parallel predicated tail
        const int rem = end - i;
        int2 ee[7];
#pragma unroll
        for (int u = 0; u < 7; u++)
            if (u < rem) ee[u] = g_epk[i + u];
        float2 pp[7];
#pragma unroll
        for (int u = 0; u < 7; u++)
            if (u < rem) pp[u] = __half22float2(g_XWh[(size_t)ee[u].x * 32 + lane]);
#pragma unroll
        for (int u = 0; u < 7; u++)
            if (u < rem) {
                float wt = __int_as_float(ee[u].y);
                ax += wt * pp[u].x;
                ay += wt * pp[u].y;
            }
    }

    // bias + relu -> h, stage per warp
    float2 b = reinterpret_cast<const float2*>(bcons)[lane];
    shh[w][2 * lane]     = fmaxf(ax + b.x, 0.0f);
    shh[w][2 * lane + 1] = fmaxf(ay + b.y, 0.0f);
    __syncwarp();

    // G[node] = h @ W_cls  (lanes 0..19, two columns each)
    if (lane < 20) {
        float gx = 0.0f, gy = 0.0f;
#pragma unroll
        for (int k = 0; k < 64; k++) {
            float hk = shh[w][k];
            gx += hk * sWc[k * 42 + 2 * lane];
            gy += hk * sWc[k * 42 + 2 * lane + 1];
        }
        g_Gh[(size_t)node * 20 + lane] = __floats2half2_rn(gx, gy);
    }
}

// ---------------- layer-2 aggregation ----------------
__global__ void k_agg2(float* __restrict__ out, const float* __restrict__ bcls, int E) {
    int node = (blockIdx.x * blockDim.x + threadIdx.x) >> 5;
    int lane = threadIdx.x & 31;
    if (node >= NN) return;
    const int beg = csr_off(node, E);
    const int end = csr_off(node + 1, E);

    const int cl = (lane < 20) ? lane : 0;

    float dd = g_dinv[node]; dd *= dd;
    float2 v0 = __half22float2(g_Gh[(size_t)node * 20 + cl]);
    float ax = dd * v0.x, ay = dd * v0.y;

    int i = beg;
    for (; i + 8 <= end; i += 8) {
        int2 ee[8];
#pragma unroll
        for (int u = 0; u < 8; u++) ee[u] = g_epk[i + u];
        float2 pp[8];
#pragma unroll
        for (int u = 0; u < 8; u++) pp[u] = __half22float2(g_Gh[(size_t)ee[u].x * 20 + cl]);
#pragma unroll
        for (int u = 0; u < 8; u++) {
            float wt = __int_as_float(ee[u].y);
            ax += wt * pp[u].x;
            ay += wt * pp[u].y;
        }
    }
    {
        const int rem = end - i;
        int2 ee[7];
#pragma unroll
        for (int u = 0; u < 7; u++)
            if (u < rem) ee[u] = g_epk[i + u];
        float2 pp[7];
#pragma unroll
        for (int u = 0; u < 7; u++)
            if (u < rem) pp[u] = __half22float2(g_Gh[(size_t)ee[u].x * 20 + cl]);
#pragma unroll
        for (int u = 0; u < 7; u++)
            if (u < rem) {
                float wt = __int_as_float(ee[u].y);
                ax += wt * pp[u].x;
                ay += wt * pp[u].y;
            }
    }

    if (lane < 20) {
        float2 b = reinterpret_cast<const float2*>(bcls)[lane];
        reinterpret_cast<float2*>(out)[(size_t)node * 20 + lane] =
            make_float2(ax + b.x, ay + b.y);
    }
}

// ---------------- launch ----------------
extern "C" void kernel_launch(void* const* d_in, const int* in_sizes, int n_in,
                              void* d_out, int out_size) {
    const float* x     = (const float*)d_in[0];
    const int*   ei    = (const int*)  d_in[1];
    const float* Wcons = (const float*)d_in[2];
    const float* bcons = (const float*)d_in[3];
    const float* Wcls  = (const float*)d_in[4];
    const float* bcls  = (const float*)d_in[5];
    const int E = in_sizes[1] / 2;
    const int* src = ei;
    const int* dst = ei + E;
    float* out = (float*)d_out;

    cudaStream_t s2;
    cudaStreamCreateWithFlags(&s2, cudaStreamNonBlocking);
    cudaEvent_t evF, evJ;
    cudaEventCreateWithFlags(&evF, cudaEventDisableTiming);
    cudaEventCreateWithFlags(&evJ, cudaEventDisableTiming);

    // fork BEFORE gemm1 so the CSR chain runs in parallel with it
    cudaEventRecord(evF, 0);
    cudaStreamWaitEvent(s2, evF, 0);

    // main stream: gemm1
    k_gemm1<<<(NN + 127) / 128, 256>>>(x, Wcons);

    // s2: degree + CSR build
    k_count     <<<(E + 255) / 256, 256, 0, s2>>>(dst, E);
    k_scan_block<<<NB, 256, 0, s2>>>();
    k_scan_tops <<<1, 512, 0, s2>>>();
    k_fill      <<<(E + 255) / 256, 256, 0, s2>>>(src, dst, E);
    cudaEventRecord(evJ, s2);

    // join, then fused agg1+gemm2, then agg2
    cudaStreamWaitEvent(0, evJ, 0);
    k_agg1<<<NN / 8, 256>>>(bcons, Wcls, E);
    k_agg2<<<(NN * 32 + 255) / 256, 256>>>(out, bcls, E);
}

// round 13
// speedup vs baseline: 1.0319x; 1.0319x over previous
#include <cuda_runtime.h>
#include <cuda_fp16.h>
#include <cstdint>

#define NN    100000
#define INCH  500
#define HID   64
#define OUTC  40
#define EMAX  3200000
#define NB    ((NN + 255) / 256)   // scan blocks = 391

// ---------------- scratch (device globals; zero-initialized at load) ----------------
__device__ float   g_dinv[NN];
__device__ int     g_cnt[NN];       // always zero between calls (scan_block re-zeroes)
__device__ int     g_off[NN];       // per-block exclusive scan (bscan folded lazily)
__device__ int     g_cur[NN];       // always zero between calls
__device__ int     g_bsum[512];
__device__ int     g_bscan[512];
__device__ int2    g_epk[EMAX];                 // (src, bitcast(weight)) grouped by dst
__device__ __half2 g_XWh[(size_t)NN * 32];      // x @ W_cons, fp16 pairs
__device__ float   g_H [(size_t)NN * HID];      // relu(agg1 + b_cons), fp32
__device__ __half2 g_Gh[(size_t)NN * 20];       // H @ W_cls, fp16 pairs

__device__ __forceinline__ int csr_off(int i, int E) {
    return (i >= NN) ? E : (g_off[i] + g_bscan[i >> 8]);
}

// ---------------- degree count ----------------
__global__ void k_count(const int* __restrict__ dst, int E) {
    int e = blockIdx.x * blockDim.x + threadIdx.x;
    if (e < E) atomicAdd(&g_cnt[dst[e]], 1);
}

// ---------------- per-block exclusive scan (dinv + re-zero fused) ----------------
__global__ void k_scan_block() {
    __shared__ int sh[256];
    int b = blockIdx.x, t = threadIdx.x;
    int i = b * 256 + t;
    int v = (i < NN) ? g_cnt[i] : 0;
    if (i < NN) {
        g_dinv[i] = rsqrtf((float)(v + 1));
        g_cnt[i] = 0;
        g_cur[i] = 0;
    }
    int x = v;
    sh[t] = x; __syncthreads();
#pragma unroll
    for (int d = 1; d < 256; d <<= 1) {
        int y = (t >= d) ? sh[t - d] : 0;
        __syncthreads();
        x += y; sh[t] = x;
        __syncthreads();
    }
    if (i < NN) g_off[i] = x - v;
    if (t == 255) g_bsum[b] = x;
}
__global__ void k_scan_tops() {
    __shared__ int sh[512];
    int t = threadIdx.x;
    int v = (t < NB) ? g_bsum[t] : 0;
    int x = v;
    sh[t] = x; __syncthreads();
#pragma unroll
    for (int d = 1; d < 512; d <<= 1) {
        int y = (t >= d) ? sh[t - d] : 0;
        __syncthreads();
        x += y; sh[t] = x;
        __syncthreads();
    }
    if (t < NB) g_bscan[t] = x - v;
}

// ---------------- CSR fill ----------------
__global__ void k_fill(const int* __restrict__ src, const int* __restrict__ dst, int E) {
    int e = blockIdx.x * blockDim.x + threadIdx.x;
    if (e >= E) return;
    int s = src[e];
    int d = dst[e];
    int pos = g_off[d] + g_bscan[d >> 8] + atomicAdd(&g_cur[d], 1);
    g_epk[pos] = make_int2(s, __float_as_int(g_dinv[s] * g_dinv[d]));
}

// ---------------- GEMM1 (tf32, K-tile 16, reg-prefetch, high occupancy) ----------------
__device__ __forceinline__ uint32_t f2tf32(float f) {
    uint32_t r;
    asm("cvt.rna.tf32.f32 %0, %1;" : "=r"(r) : "f"(f));
    return r;
}
__device__ __forceinline__ void mma_tf32(float* d, const uint32_t* a, const uint32_t* b) {
    asm volatile(
        "mma.sync.aligned.m16n8k8.row.col.f32.tf32.tf32.f32 "
        "{%0,%1,%2,%3}, {%4,%5,%6,%7}, {%8,%9}, {%0,%1,%2,%3};"
        : "+f"(d[0]), "+f"(d[1]), "+f"(d[2]), "+f"(d[3])
        : "r"(a[0]), "r"(a[1]), "r"(a[2]), "r"(a[3]), "r"(b[0]), "r"(b[1]));
}

// stage loads: A 128 rows x 16 k (512 float4, 2/thread), B 16 k x 64 cols (256 float4, 1/thread)
__device__ __forceinline__ void g1_load(const float* __restrict__ X,
                                        const float* __restrict__ W,
                                        int row0, int k0, int tid,
                                        float4 aR[2], float4& bR) {
    const int kq = (INCH - k0 >= 16) ? 4 : (INCH - k0) / 4;   // valid float4s along k (4 or 1)
#pragma unroll
    for (int n = 0; n < 2; n++) {
        int i = tid + n * 256;
        int r = i >> 2, q = i & 3;
        int gr = row0 + r;
        aR[n] = (gr < NN && q < kq)
            ? *reinterpret_cast<const float4*>(X + (size_t)gr * INCH + k0 + q * 4)
            : make_float4(0.f, 0.f, 0.f, 0.f);
    }
    {
        int kk = tid >> 4, cq = tid & 15;
        bR = (k0 + kk < INCH)
            ? *reinterpret_cast<const float4*>(W + (size_t)(k0 + kk) * HID + cq * 4)
            : make_float4(0.f, 0.f, 0.f, 0.f);
    }
}

__global__ void __launch_bounds__(256) k_gemm1(const float* __restrict__ X,
                                               const float* __restrict__ W) {
    __shared__ uint32_t As[16][132];   // [kk][row] tf32 bits, pad 4
    __shared__ uint32_t Bs[16][68];    // [kk][col] tf32 bits, pad 4

    const int row0 = blockIdx.x * 128;
    const int tid  = threadIdx.x;
    const int lane = tid & 31;
    const int wid  = tid >> 5;
    const int wm   = wid & 3;          // warp M group (32 rows)
    const int wn   = wid >> 2;         // warp N group (32 cols)
    const int g    = lane >> 2;        // 0..7
    const int q4   = lane & 3;         // 0..3

    float acc[2][4][4];
#pragma unroll
    for (int tm = 0; tm < 2; tm++)
#pragma unroll
        for (int tn = 0; tn < 4; tn++)
#pragma unroll
            for (int j = 0; j < 4; j++) acc[tm][tn][j] = 0.0f;

    float4 aR[2];
    float4 bR;
    g1_load(X, W, row0, 0, tid, aR, bR);

    const int NT = (INCH + 15) / 16;   // 32
    for (int kt = 0; kt < NT; kt++) {
        // staged regs -> smem (tf32 convert)
#pragma unroll
        for (int n = 0; n < 2; n++) {
            int i = tid + n * 256;
            int r = i >> 2, q = i & 3;
            As[q * 4 + 0][r] = f2tf32(aR[n].x);
            As[q * 4 + 1][r] = f2tf32(aR[n].y);
            As[q * 4 + 2][r] = f2tf32(aR[n].z);
            As[q * 4 + 3][r] = f2tf32(aR[n].w);
        }
        {
            int kk = tid >> 4, cq = tid & 15;
            Bs[kk][cq * 4 + 0] = f2tf32(bR.x);
            Bs[kk][cq * 4 + 1] = f2tf32(bR.y);
            Bs[kk][cq * 4 + 2] = f2tf32(bR.z);
            Bs[kk][cq * 4 + 3] = f2tf32(bR.w);
        }
        __syncthreads();

        // prefetch next tile into regs (overlaps MMA below)
        if (kt + 1 < NT) g1_load(X, W, row0, (kt + 1) * 16, tid, aR, bR);

#pragma unroll
        for (int ks = 0; ks < 2; ks++) {
            const int kk = ks * 8 + q4;
            uint32_t a[2][4];
#pragma unroll
            for (int tm = 0; tm < 2; tm++) {
                int r = wm * 32 + tm * 16 + g;
                a[tm][0] = As[kk][r];
                a[tm][1] = As[kk][r + 8];
                a[tm][2] = As[kk + 4][r];
                a[tm][3] = As[kk + 4][r + 8];
            }
            uint32_t b[4][2];
#pragma unroll
            for (int tn = 0; tn < 4; tn++) {
                int c = wn * 32 + tn * 8 + g;
                b[tn][0] = Bs[kk][c];
                b[tn][1] = Bs[kk + 4][c];
            }
#pragma unroll
            for (int tm = 0; tm < 2; tm++)
#pragma unroll
                for (int tn = 0; tn < 4; tn++)
                    mma_tf32(acc[tm][tn], a[tm], b[tn]);
        }
        __syncthreads();
    }

#pragma unroll
    for (int tm = 0; tm < 2; tm++) {
#pragma unroll
        for (int tn = 0; tn < 4; tn++) {
            int c2 = (wn * 32 + tn * 8 + q4 * 2) >> 1;
            int r = row0 + wm * 32 + tm * 16 + g;
            if (r < NN)
                g_XWh[(size_t)r * 32 + c2] = __floats2half2_rn(acc[tm][tn][0], acc[tm][tn][1]);
            if (r + 8 < NN)
                g_XWh[(size_t)(r + 8) * 32 + c2] = __floats2half2_rn(acc[tm][tn][2], acc[tm][tn][3]);
        }
    }
}

// ---------------- layer-1 aggregation: warp/node, fp16 gathers ----------------
__global__ void k_agg1(const float* __restrict__ bcons, int E) {
    int node = (blockIdx.x * blockDim.x + threadIdx.x) >> 5;
    int lane = threadIdx.x & 31;
    if (node >= NN) return;
    const int beg = csr_off(node, E);
    const int end = csr_off(node + 1, E);

    float dd = g_dinv[node]; dd *= dd;
    float2 v0 = __half22float2(g_XWh[(size_t)node * 32 + lane]);
    float ax = dd * v0.x, ay = dd * v0.y;

    int i = beg;
    for (; i + 8 <= end; i += 8) {
        int2 ee[8];
#pragma unroll
        for (int u = 0; u < 8; u++) ee[u] = g_epk[i + u];
        float2 pp[8];
#pragma unroll
        for (int u = 0; u < 8; u++) pp[u] = __half22float2(g_XWh[(size_t)ee[u].x * 32 + lane]);
#pragma unroll
        for (int u = 0; u < 8; u++) {
            float wt = __int_as_float(ee[u].y);
            ax += wt * pp[u].x;
            ay += wt * pp[u].y;
        }
    }
    {   // parallel predicated tail
        const int rem = end - i;
        int2 ee[7];
#pragma unroll
        for (int u = 0; u < 7; u++)
            if (u < rem) ee[u] = g_epk[i + u];
        float2 pp[7];
#pragma unroll
        for (int u = 0; u < 7; u++)
            if (u < rem) pp[u] = __half22float2(g_XWh[(size_t)ee[u].x * 32 + lane]);
#pragma unroll
        for (int u = 0; u < 7; u++)
            if (u < rem) {
                float wt = __int_as_float(ee[u].y);
                ax += wt * pp[u].x;
                ay += wt * pp[u].y;
            }
    }

    float2 b = reinterpret_cast<const float2*>(bcons)[lane];
    float2 h = make_float2(fmaxf(ax + b.x, 0.0f), fmaxf(ay + b.y, 0.0f));
    reinterpret_cast<float2*>(g_H)[(size_t)node * 32 + lane] = h;
}

// ---------------- GEMM2: Gh = H @ W_cls  [100000 x 64] @ [64 x 40] ----------------
__global__ void __launch_bounds__(320) k_gemm2(const float* __restrict__ Wc) {
    __shared__ float Hs[64][65];
    __shared__ float Ws[64][40];   // reused as G staging

    const int row0 = blockIdx.x * 64;
    const int tid  = threadIdx.x;

    for (int i = tid; i < 64 * 64; i += 320) {
        int r = i >> 6, k = i & 63;
        int gr = row0 + r;
        Hs[r][k] = (gr < NN) ? g_H[(size_t)gr * HID + k] : 0.0f;
    }
    for (int i = tid; i < 64 * 40; i += 320) {
        int k = i / 40, c = i - k * 40;
        Ws[k][c] = Wc[(size_t)k * OUTC + c];
    }
    __syncthreads();

    const int r = tid / 40;
    const int c = tid - r * 40;
    float acc[8];
#pragma unroll
    for (int j = 0; j < 8; j++) acc[j] = 0.0f;

#pragma unroll
    for (int k = 0; k < 64; k++) {
        float w = Ws[k][c];
#pragma unroll
        for (int j = 0; j < 8; j++) acc[j] += Hs[r + j * 8][k] * w;
    }
    __syncthreads();
#pragma unroll
    for (int j = 0; j < 8; j++) Ws[r + j * 8][c] = acc[j];
    __syncthreads();

    for (int i = tid; i < 64 * 20; i += 320) {
        int rr = i / 20, c2 = i - rr * 20;
        int gr = row0 + rr;
        if (gr < NN)
            g_Gh[(size_t)gr * 20 + c2] = __floats2half2_rn(Ws[rr][c2 * 2], Ws[rr][c2 * 2 + 1]);
    }
}

// ---------------- layer-2 aggregation ----------------
__global__ void k_agg2(float* __restrict__ out, const float* __restrict__ bcls, int E) {
    int node = (blockIdx.x * blockDim.x + threadIdx.x) >> 5;
    int lane = threadIdx.x & 31;
    if (node >= NN) return;
    const int beg = csr_off(node, E);
    const int end = csr_off(node + 1, E);

    const int cl = (lane < 20) ? lane : 0;

    float dd = g_dinv[node]; dd *= dd;
    float2 v0 = __half22float2(g_Gh[(size_t)node * 20 + cl]);
    float ax = dd * v0.x, ay = dd * v0.y;

    int i = beg;
    for (; i + 8 <= end; i += 8) {
        int2 ee[8];
#pragma unroll
        for (int u = 0; u < 8; u++) ee[u] = g_epk[i + u];
        float2 pp[8];
#pragma unroll
        for (int u = 0; u < 8; u++) pp[u] = __half22float2(g_Gh[(size_t)ee[u].x * 20 + cl]);
#pragma unroll
        for (int u = 0; u < 8; u++) {
            float wt = __int_as_float(ee[u].y);
            ax += wt * pp[u].x;
            ay += wt * pp[u].y;
        }
    }
    {
        const int rem = end - i;
        int2 ee[7];
#pragma unroll
        for (int u = 0; u < 7; u++)
            if (u < rem) ee[u] = g_epk[i + u];
        float2 pp[7];
#pragma unroll
        for (int u = 0; u < 7; u++)
            if (u < rem) pp[u] = __half22float2(g_Gh[(size_t)ee[u].x * 20 + cl]);
#pragma unroll
        for (int u = 0; u < 7; u++)
            if (u < rem) {
                float wt = __int_as_float(ee[u].y);
                ax += wt * pp[u].x;
                ay += wt * pp[u].y;
            }
    }

    if (lane < 20) {
        float2 b = reinterpret_cast<const float2*>(bcls)[lane];
        reinterpret_cast<float2*>(out)[(size_t)node * 20 + lane] =
            make_float2(ax + b.x, ay + b.y);
    }
}

// ---------------- launch ----------------
extern "C" void kernel_launch(void* const* d_in, const int* in_sizes, int n_in,
                              void* d_out, int out_size) {
    const float* x     = (const float*)d_in[0];
    const int*   ei    = (const int*)  d_in[1];
    const float* Wcons = (const float*)d_in[2];
    const float* bcons = (const float*)d_in[3];
    const float* Wcls  = (const float*)d_in[4];
    const float* bcls  = (const float*)d_in[5];
    const int E = in_sizes[1] / 2;
    const int* src = ei;
    const int* dst = ei + E;
    float* out = (float*)d_out;

    cudaStream_t s2;
    cudaStreamCreateWithFlags(&s2, cudaStreamNonBlocking);
    cudaEvent_t evF, evJ;
    cudaEventCreateWithFlags(&evF, cudaEventDisableTiming);
    cudaEventCreateWithFlags(&evJ, cudaEventDisableTiming);

    // fork BEFORE gemm1 so the CSR chain runs in parallel with it
    cudaEventRecord(evF, 0);
    cudaStreamWaitEvent(s2, evF, 0);

    // main stream: gemm1
    k_gemm1<<<(NN + 127) / 128, 256>>>(x, Wcons);

    // s2: degree + CSR build
    k_count     <<<(E + 255) / 256, 256, 0, s2>>>(dst, E);
    k_scan_block<<<NB, 256, 0, s2>>>();
    k_scan_tops <<<1, 512, 0, s2>>>();
    k_fill      <<<(E + 255) / 256, 256, 0, s2>>>(src, dst, E);
    cudaEventRecord(evJ, s2);

    // join, then agg1, gemm2, agg2
    cudaStreamWaitEvent(0, evJ, 0);
    k_agg1<<<(NN * 32 + 255) / 256, 256>>>(bcons, E);
    k_gemm2<<<(NN + 63) / 64, 320>>>(Wcls);
    k_agg2<<<(NN * 32 + 255) / 256, 256>>>(out, bcls, E);
}